// round 1
// baseline (speedup 1.0000x reference)
#include <cuda_runtime.h>
#include <math.h>

// Problem constants
#define T_TOK 4096
#define H_DIM 1024
#define I_DIM 2048
#define N_EXP 8
#define K_TOP 2
#define MAXROWS 10240   // 8192 pairs + up to 8*128 padding, rounded up (80 tiles of 128)

// Scratch (device globals — allocation-free per harness rules)
__device__ int   d_count[N_EXP];
__device__ int   d_cursor[N_EXP];
__device__ int   d_seg[N_EXP + 1];           // padded segment starts; d_seg[8] = total padded rows
__device__ int   d_tok[MAXROWS];             // token id per row (-1 = padding)
__device__ int   d_pairrow[T_TOK * K_TOP];   // (token,k) -> row
__device__ float d_topw[T_TOK * K_TOP];      // combine weights (top-2 softmax probs)
__device__ int   d_tope[T_TOK * K_TOP];      // expert ids
__device__ float d_g [(size_t)MAXROWS * I_DIM];  // gate proj, then mid (in-place)
__device__ float d_u [(size_t)MAXROWS * I_DIM];  // up proj
__device__ float d_eo[(size_t)MAXROWS * H_DIM];  // per-pair expert output

// ---------------------------------------------------------------------------
__global__ void init_kernel() {
    int tid = threadIdx.x;
    if (tid < N_EXP) { d_count[tid] = 0; d_cursor[tid] = 0; }
    for (int i = tid; i < MAXROWS; i += blockDim.x) d_tok[i] = -1;
}

// One warp per token: logits, softmax, top-2, expert counting.
__global__ void router_kernel(const float* __restrict__ x,
                              const float* __restrict__ gw,
                              float* __restrict__ out_logits) {
    int warp = threadIdx.x >> 5, lane = threadIdx.x & 31;
    int t = blockIdx.x * 8 + warp;
    if (t >= T_TOK) return;

    const float* xr = x + (size_t)t * H_DIM;
    float acc[N_EXP];
#pragma unroll
    for (int e = 0; e < N_EXP; e++) acc[e] = 0.f;

    for (int i = lane; i < H_DIM; i += 32) {
        float xv = xr[i];
        float4 a = __ldg((const float4*)(gw + (size_t)i * N_EXP));
        float4 b = __ldg((const float4*)(gw + (size_t)i * N_EXP) + 1);
        acc[0] += xv * a.x; acc[1] += xv * a.y; acc[2] += xv * a.z; acc[3] += xv * a.w;
        acc[4] += xv * b.x; acc[5] += xv * b.y; acc[6] += xv * b.z; acc[7] += xv * b.w;
    }
#pragma unroll
    for (int off = 16; off > 0; off >>= 1)
#pragma unroll
        for (int e = 0; e < N_EXP; e++)
            acc[e] += __shfl_xor_sync(0xffffffffu, acc[e], off);

    if (lane == 0) {
#pragma unroll
        for (int e = 0; e < N_EXP; e++) out_logits[(size_t)t * N_EXP + e] = acc[e];

        float m = acc[0];
#pragma unroll
        for (int e = 1; e < N_EXP; e++) m = fmaxf(m, acc[e]);
        float p[N_EXP], s = 0.f;
#pragma unroll
        for (int e = 0; e < N_EXP; e++) { p[e] = expf(acc[e] - m); s += p[e]; }
        float inv = 1.f / s;

        int i0 = 0; float b0 = p[0];
#pragma unroll
        for (int e = 1; e < N_EXP; e++) if (p[e] > b0) { b0 = p[e]; i0 = e; }
        int i1 = -1; float b1 = -1.f;
#pragma unroll
        for (int e = 0; e < N_EXP; e++) if (e != i0 && p[e] > b1) { b1 = p[e]; i1 = e; }

        d_tope[t * 2 + 0] = i0; d_topw[t * 2 + 0] = b0 * inv;
        d_tope[t * 2 + 1] = i1; d_topw[t * 2 + 1] = b1 * inv;
        atomicAdd(&d_count[i0], 1);
        atomicAdd(&d_count[i1], 1);
    }
}

// Padded prefix sum over 8 expert counts (align segments to 128-row tiles).
__global__ void scan_kernel() {
    if (threadIdx.x == 0) {
        int off = 0;
#pragma unroll
        for (int e = 0; e < N_EXP; e++) {
            d_seg[e] = off;
            off += (d_count[e] + 127) & ~127;
        }
        d_seg[N_EXP] = off;
    }
}

__global__ void scatter_kernel() {
    int t = blockIdx.x * blockDim.x + threadIdx.x;
    if (t >= T_TOK) return;
#pragma unroll
    for (int k = 0; k < K_TOP; k++) {
        int e = d_tope[t * 2 + k];
        int pos = atomicAdd(&d_cursor[e], 1);
        int row = d_seg[e] + pos;
        d_tok[row] = t;
        d_pairrow[t * 2 + k] = row;
    }
}

// ---------------------------------------------------------------------------
// Grouped SGEMM: C[row, n] = sum_k A[row, k] * B[expert(row)][k, n]
// mode 0: A = gather(x), C = d_g  (gate)
// mode 1: A = gather(x), C = d_u  (up)
// mode 2: A = d_g (mid, direct), C = d_eo (down)
// 128x128 tile, BK=8, 256 threads, 8x8 per-thread microtile.
__global__ __launch_bounds__(256, 2)
void gemm_kernel(const float* __restrict__ X, const float* __restrict__ B,
                 int Kdim, int N, int mode) {
    __shared__ __align__(16) float As[8][128];
    __shared__ __align__(16) float Bs[8][128];

    int row0 = blockIdx.x * 128;
    if (row0 >= d_seg[N_EXP]) return;
    int e = 0;
#pragma unroll
    for (int i = 0; i < N_EXP - 1; i++) if (row0 >= d_seg[i + 1]) e = i + 1;

    const float* Bex = B + (size_t)e * Kdim * N;
    int n0 = blockIdx.y * 128;
    int tid = threadIdx.x;

    int arow = tid >> 1, ak4 = (tid & 1) << 2;
    const float* Arow;
    if (mode < 2) {
        int tok = d_tok[row0 + arow];
        Arow = (tok >= 0) ? X + (size_t)tok * Kdim : nullptr;
    } else {
        Arow = d_g + (size_t)(row0 + arow) * Kdim;
    }
    int bk = tid >> 5, bn4 = (tid & 31) << 2;
    const float* Bptr = Bex + (size_t)bk * N + n0 + bn4;

    int tx = tid & 15, ty = tid >> 4;
    float acc[8][8] = {};

    for (int k0 = 0; k0 < Kdim; k0 += 8) {
        float4 av = Arow ? *(const float4*)(Arow + k0 + ak4)
                         : make_float4(0.f, 0.f, 0.f, 0.f);
        float4 bv = *(const float4*)(Bptr + (size_t)k0 * N);
        __syncthreads();
        As[ak4 + 0][arow] = av.x; As[ak4 + 1][arow] = av.y;
        As[ak4 + 2][arow] = av.z; As[ak4 + 3][arow] = av.w;
        *(float4*)&Bs[bk][bn4] = bv;
        __syncthreads();
#pragma unroll
        for (int k = 0; k < 8; k++) {
            float a[8], b[8];
#pragma unroll
            for (int i = 0; i < 8; i++) a[i] = As[k][ty * 8 + i];
#pragma unroll
            for (int j = 0; j < 8; j++) b[j] = Bs[k][tx * 8 + j];
#pragma unroll
            for (int i = 0; i < 8; i++)
#pragma unroll
                for (int j = 0; j < 8; j++) acc[i][j] += a[i] * b[j];
        }
    }

    float* Cbase = (mode == 0) ? d_g : (mode == 1) ? d_u : d_eo;
#pragma unroll
    for (int i = 0; i < 8; i++) {
        float* crow = Cbase + (size_t)(row0 + ty * 8 + i) * N + n0 + tx * 8;
        *(float4*)(crow)     = make_float4(acc[i][0], acc[i][1], acc[i][2], acc[i][3]);
        *(float4*)(crow + 4) = make_float4(acc[i][4], acc[i][5], acc[i][6], acc[i][7]);
    }
}

// mid = silu(g) * u, in place into d_g.
__global__ void act_kernel() {
    size_t idx = (size_t)blockIdx.x * blockDim.x + threadIdx.x;  // float4 index
    int row = (int)((idx * 4) / I_DIM);
    if (row >= d_seg[N_EXP]) return;
    float4 g = ((const float4*)d_g)[idx];
    float4 u = ((const float4*)d_u)[idx];
    g.x = g.x / (1.f + expf(-g.x)) * u.x;
    g.y = g.y / (1.f + expf(-g.y)) * u.y;
    g.z = g.z / (1.f + expf(-g.z)) * u.z;
    g.w = g.w / (1.f + expf(-g.w)) * u.w;
    ((float4*)d_g)[idx] = g;
}

// out[t] = w0*eo[row0] + w1*eo[row1]
__global__ void combine_kernel(float* __restrict__ out) {
    int t = blockIdx.x;
    int r0 = d_pairrow[t * 2 + 0], r1 = d_pairrow[t * 2 + 1];
    float w0 = d_topw[t * 2 + 0], w1 = d_topw[t * 2 + 1];
    int h4 = threadIdx.x;  // 256 threads x float4 = 1024 floats
    float4 a = ((const float4*)(d_eo + (size_t)r0 * H_DIM))[h4];
    float4 b = ((const float4*)(d_eo + (size_t)r1 * H_DIM))[h4];
    float4 o;
    o.x = w0 * a.x + w1 * b.x;
    o.y = w0 * a.y + w1 * b.y;
    o.z = w0 * a.z + w1 * b.z;
    o.w = w0 * a.w + w1 * b.w;
    ((float4*)(out + (size_t)t * H_DIM))[h4] = o;
}

// ---------------------------------------------------------------------------
extern "C" void kernel_launch(void* const* d_in, const int* in_sizes, int n_in,
                              void* d_out, int out_size) {
    const float* x  = (const float*)d_in[0];  // [4096, 1024]
    const float* gw = (const float*)d_in[1];  // [1024, 8]
    const float* Wg = (const float*)d_in[2];  // [8, 1024, 2048]
    const float* Wu = (const float*)d_in[3];  // [8, 1024, 2048]
    const float* Wd = (const float*)d_in[4];  // [8, 2048, 1024]
    float* out = (float*)d_out;               // final (4194304) then logits (32768)

    float* out_logits = out + (size_t)T_TOK * H_DIM;

    init_kernel<<<1, 256>>>();
    router_kernel<<<T_TOK / 8, 256>>>(x, gw, out_logits);
    scan_kernel<<<1, 32>>>();
    scatter_kernel<<<T_TOK / 256, 256>>>();

    gemm_kernel<<<dim3(MAXROWS / 128, I_DIM / 128), 256>>>(x, Wg, H_DIM, I_DIM, 0);
    gemm_kernel<<<dim3(MAXROWS / 128, I_DIM / 128), 256>>>(x, Wu, H_DIM, I_DIM, 1);
    act_kernel<<<(MAXROWS * (I_DIM / 4)) / 256, 256>>>();
    gemm_kernel<<<dim3(MAXROWS / 128, H_DIM / 128), 256>>>(x, Wd, I_DIM, H_DIM, 2);
    combine_kernel<<<T_TOK, 256>>>(out);
}

// round 4
// speedup vs baseline: 2.6682x; 2.6682x over previous
#include <cuda_runtime.h>
#include <cuda_bf16.h>
#include <cstdint>
#include <math.h>

// ---------------------------------------------------------------------------
// Problem constants
#define T_TOK 4096
#define H_DIM 1024
#define I_DIM 2048
#define N_EXP 8
#define K_TOP 2
#define MAXROWS 10240   // 8192 pairs + per-expert padding to 128 => 80 tiles

// GEMM tiling
#define BM 128
#define BN 128
#define BK 32
#define ROWB 80                      // padded smem row: 32 bf16 (64B) + 16B pad
#define TILE_BYTES (128 * ROWB)      // 10240
#define STAGE_BYTES (4 * TILE_BYTES) // Ahi, Alo, Bhi, Blo
#define SMEM_TOTAL (2 * STAGE_BYTES) // 81920

// ---------------------------------------------------------------------------
// Scratch (device globals — allocation-free; referenced ONLY from device code)
__device__ int   d_count[N_EXP];
__device__ int   d_cursor[N_EXP];
__device__ int   d_seg[N_EXP + 1];
__device__ int   d_tok[MAXROWS];
__device__ int   d_pairrow[T_TOK * K_TOP];
__device__ float d_topw[T_TOK * K_TOP];
__device__ int   d_tope[T_TOK * K_TOP];

__device__ unsigned short d_xhi[(size_t)T_TOK * H_DIM];
__device__ unsigned short d_xlo[(size_t)T_TOK * H_DIM];
// W1 = [Wg | Wu] transposed: [E][4096][1024]  (n-major, k contiguous)
__device__ unsigned short d_W1hi[(size_t)N_EXP * 2 * I_DIM * H_DIM];
__device__ unsigned short d_W1lo[(size_t)N_EXP * 2 * I_DIM * H_DIM];
// Wd transposed: [E][1024][2048]
__device__ unsigned short d_Wdhi[(size_t)N_EXP * H_DIM * I_DIM];
__device__ unsigned short d_Wdlo[(size_t)N_EXP * H_DIM * I_DIM];
__device__ unsigned short d_midhi[(size_t)MAXROWS * I_DIM];
__device__ unsigned short d_midlo[(size_t)MAXROWS * I_DIM];
__device__ float d_g [(size_t)MAXROWS * I_DIM];
__device__ float d_u [(size_t)MAXROWS * I_DIM];
__device__ float d_eo[(size_t)MAXROWS * H_DIM];

// ---------------------------------------------------------------------------
// PTX macros (baseline PTX only: compiles for compute_103 target)
#define CP16(dst, src, sz) \
    asm volatile("cp.async.ca.shared.global [%0], [%1], 16, %2;" \
                 :: "r"(dst), "l"(src), "r"(sz) : "memory")
#define CP_COMMIT() asm volatile("cp.async.commit_group;" ::: "memory")
#define CP_WAIT1()  asm volatile("cp.async.wait_group 1;" ::: "memory")
#define CP_WAIT0()  asm volatile("cp.async.wait_group 0;" ::: "memory")

#define LDSM_X4(r, addr) \
    asm volatile("ldmatrix.sync.aligned.m8n8.x4.shared.b16 {%0,%1,%2,%3}, [%4];" \
                 : "=r"((r)[0]), "=r"((r)[1]), "=r"((r)[2]), "=r"((r)[3]) : "r"(addr))

#define MMA_BF16(c, a, b) \
    asm volatile("mma.sync.aligned.m16n8k16.row.col.f32.bf16.bf16.f32 " \
                 "{%0,%1,%2,%3}, {%4,%5,%6,%7}, {%8,%9}, {%0,%1,%2,%3};" \
                 : "+f"((c)[0]), "+f"((c)[1]), "+f"((c)[2]), "+f"((c)[3]) \
                 : "r"((a)[0]), "r"((a)[1]), "r"((a)[2]), "r"((a)[3]), \
                   "r"((b)[0]), "r"((b)[1]))

// bf16 split helpers
__device__ __forceinline__ unsigned short bfbits(float v) {
    __nv_bfloat16 b = __float2bfloat16_rn(v);
    return *reinterpret_cast<unsigned short*>(&b);
}
__device__ __forceinline__ float bfval(unsigned short u) {
    __nv_bfloat16 b;
    *reinterpret_cast<unsigned short*>(&b) = u;
    return __bfloat162float(b);
}
__device__ __forceinline__ void split2(float v, unsigned short& h, unsigned short& l) {
    h = bfbits(v);
    l = bfbits(v - bfval(h));
}

// ---------------------------------------------------------------------------
__global__ void init_kernel() {
    int tid = threadIdx.x;
    if (tid < N_EXP) { d_count[tid] = 0; d_cursor[tid] = 0; }
    for (int i = tid; i < MAXROWS; i += blockDim.x) d_tok[i] = -1;
}

// fp32 x -> bf16 hi/lo (writes device globals directly)
__global__ void convx_kernel(const float* __restrict__ x) {
    size_t i = (size_t)blockIdx.x * 256 + threadIdx.x;  // float4 index
    float4 v = ((const float4*)x)[i];
    ushort4 h, l;
    split2(v.x, h.x, l.x); split2(v.y, h.y, l.y);
    split2(v.z, h.z, l.z); split2(v.w, h.w, l.w);
    ((ushort4*)d_xhi)[i] = h;
    ((ushort4*)d_xlo)[i] = l;
}

// transpose + hi/lo split: W [E][Kd][Nd] fp32 -> dest [E][Nb][Kd] bf16.
// mode 0: Wg -> W1 at n_off 0;  mode 1: Wu -> W1 at n_off I_DIM;  mode 2: Wd.
__global__ void wtrans_kernel(const float* __restrict__ W, int mode) {
    __shared__ float tile[32][33];
    const int Kd    = (mode == 2) ? I_DIM : H_DIM;
    const int Nd    = (mode == 2) ? H_DIM : I_DIM;
    const int Nb    = (mode == 2) ? H_DIM : 2 * I_DIM;
    const int n_off = (mode == 1) ? I_DIM : 0;
    unsigned short* Thi = (mode == 2) ? d_Wdhi : d_W1hi;
    unsigned short* Tlo = (mode == 2) ? d_Wdlo : d_W1lo;

    int e = blockIdx.z;
    const float* We = W + (size_t)e * Kd * Nd;
    int nbase = blockIdx.x * 32, kbase = blockIdx.y * 32;
    int tx = threadIdx.x & 31, ty = threadIdx.x >> 5;  // 256 thr: ty 0..7
#pragma unroll
    for (int i = 0; i < 32; i += 8)
        tile[ty + i][tx] = We[(size_t)(kbase + ty + i) * Nd + nbase + tx];
    __syncthreads();
    size_t ebase = (size_t)e * Nb * Kd;
#pragma unroll
    for (int i = 0; i < 32; i += 8) {
        float v = tile[tx][ty + i];
        unsigned short h, l;
        split2(v, h, l);
        size_t o = ebase + (size_t)(n_off + nbase + ty + i) * Kd + kbase + tx;
        Thi[o] = h; Tlo[o] = l;
    }
}

// One warp per token: logits, softmax, top-2, expert counting.
__global__ void router_kernel(const float* __restrict__ x,
                              const float* __restrict__ gw,
                              float* __restrict__ out_logits) {
    int warp = threadIdx.x >> 5, lane = threadIdx.x & 31;
    int t = blockIdx.x * 8 + warp;
    if (t >= T_TOK) return;
    const float* xr = x + (size_t)t * H_DIM;
    float acc[N_EXP];
#pragma unroll
    for (int e = 0; e < N_EXP; e++) acc[e] = 0.f;
    for (int i = lane; i < H_DIM; i += 32) {
        float xv = xr[i];
        float4 a = __ldg((const float4*)(gw + (size_t)i * N_EXP));
        float4 b = __ldg((const float4*)(gw + (size_t)i * N_EXP) + 1);
        acc[0] += xv * a.x; acc[1] += xv * a.y; acc[2] += xv * a.z; acc[3] += xv * a.w;
        acc[4] += xv * b.x; acc[5] += xv * b.y; acc[6] += xv * b.z; acc[7] += xv * b.w;
    }
#pragma unroll
    for (int off = 16; off > 0; off >>= 1)
#pragma unroll
        for (int e = 0; e < N_EXP; e++)
            acc[e] += __shfl_xor_sync(0xffffffffu, acc[e], off);
    if (lane == 0) {
#pragma unroll
        for (int e = 0; e < N_EXP; e++) out_logits[(size_t)t * N_EXP + e] = acc[e];
        float m = acc[0];
#pragma unroll
        for (int e = 1; e < N_EXP; e++) m = fmaxf(m, acc[e]);
        float p[N_EXP], s = 0.f;
#pragma unroll
        for (int e = 0; e < N_EXP; e++) { p[e] = expf(acc[e] - m); s += p[e]; }
        float inv = 1.f / s;
        int i0 = 0; float b0 = p[0];
#pragma unroll
        for (int e = 1; e < N_EXP; e++) if (p[e] > b0) { b0 = p[e]; i0 = e; }
        int i1 = -1; float b1 = -1.f;
#pragma unroll
        for (int e = 0; e < N_EXP; e++) if (e != i0 && p[e] > b1) { b1 = p[e]; i1 = e; }
        d_tope[t * 2 + 0] = i0; d_topw[t * 2 + 0] = b0 * inv;
        d_tope[t * 2 + 1] = i1; d_topw[t * 2 + 1] = b1 * inv;
        atomicAdd(&d_count[i0], 1);
        atomicAdd(&d_count[i1], 1);
    }
}

__global__ void scan_kernel() {
    if (threadIdx.x == 0) {
        int off = 0;
#pragma unroll
        for (int e = 0; e < N_EXP; e++) { d_seg[e] = off; off += (d_count[e] + 127) & ~127; }
        d_seg[N_EXP] = off;
    }
}

__global__ void scatter_kernel() {
    int t = blockIdx.x * blockDim.x + threadIdx.x;
    if (t >= T_TOK) return;
#pragma unroll
    for (int k = 0; k < K_TOP; k++) {
        int e = d_tope[t * 2 + k];
        int pos = atomicAdd(&d_cursor[e], 1);
        int row = d_seg[e] + pos;
        d_tok[row] = t;
        d_pairrow[t * 2 + k] = row;
    }
}

// ---------------------------------------------------------------------------
// Grouped GEMM on mma.sync.m16n8k16 bf16, hi/lo split (3 passes), fp32 acc.
// MODE 0: A = gather(x) [K=1024], B = W1 [E][4096][1024], C -> d_g | d_u
// MODE 1: A = mid (direct) [K=2048], B = Wd [E][1024][2048], C -> d_eo
// 128x128x32 CTA tile, 8 warps of 64x32, 2-stage cp.async pipeline.
template <int MODE>
__global__ __launch_bounds__(256, 1)
void mma_gemm_kernel()
{
    constexpr int Kdim   = (MODE == 0) ? H_DIM : I_DIM;
    constexpr int Nb     = (MODE == 0) ? 2 * I_DIM : H_DIM;
    constexpr int ldc    = (MODE == 0) ? I_DIM : H_DIM;

    extern __shared__ char sm[];
    int row0 = blockIdx.x * BM;
    if (row0 >= d_seg[N_EXP]) return;

    const unsigned short* __restrict__ Ahi_g = (MODE == 0) ? d_xhi : d_midhi;
    const unsigned short* __restrict__ Alo_g = (MODE == 0) ? d_xlo : d_midlo;
    const unsigned short* __restrict__ Bhi_g = (MODE == 0) ? d_W1hi : d_Wdhi;
    const unsigned short* __restrict__ Blo_g = (MODE == 0) ? d_W1lo : d_Wdlo;

    uint32_t sbase = (uint32_t)__cvta_generic_to_shared(sm);
    int tid = threadIdx.x, lane = tid & 31, wid = tid >> 5;
    int n0 = blockIdx.y * BN;

    int e = 0;
#pragma unroll
    for (int i = 0; i < N_EXP - 1; i++) if (row0 >= d_seg[i + 1]) e = i + 1;

    // ---- per-thread load setup: 2 rows per tile (r and r+64), 16B chunk kc
    int r1 = tid >> 2, kc = tid & 3;
    const unsigned short *pAh[2], *pAl[2], *pBh[2], *pBl[2];
    uint32_t szA[2], dstoff[2];
#pragma unroll
    for (int h2 = 0; h2 < 2; h2++) {
        int r = r1 + h2 * 64;
        dstoff[h2] = (uint32_t)(r * ROWB + kc * 16);
        if (MODE == 0) {
            int tok = d_tok[row0 + r];
            if (tok >= 0) {
                pAh[h2] = Ahi_g + (size_t)tok * Kdim + kc * 8;
                pAl[h2] = Alo_g + (size_t)tok * Kdim + kc * 8;
                szA[h2] = 16;
            } else {
                pAh[h2] = Ahi_g; pAl[h2] = Alo_g; szA[h2] = 0;  // zero-fill
            }
        } else {
            pAh[h2] = Ahi_g + (size_t)(row0 + r) * Kdim + kc * 8;
            pAl[h2] = Alo_g + (size_t)(row0 + r) * Kdim + kc * 8;
            szA[h2] = 16;
        }
        size_t bo = ((size_t)e * Nb + n0 + r) * Kdim + kc * 8;
        pBh[h2] = Bhi_g + bo;
        pBl[h2] = Blo_g + bo;
    }

#define LOAD_STAGE(s, kof) do { \
    uint32_t sb_ = sbase + (s) * STAGE_BYTES; \
    _Pragma("unroll") \
    for (int h2 = 0; h2 < 2; h2++) { \
        CP16(sb_ + 0 * TILE_BYTES + dstoff[h2], pAh[h2] + (kof), szA[h2]); \
        CP16(sb_ + 1 * TILE_BYTES + dstoff[h2], pAl[h2] + (kof), szA[h2]); \
        CP16(sb_ + 2 * TILE_BYTES + dstoff[h2], pBh[h2] + (kof), 16u); \
        CP16(sb_ + 3 * TILE_BYTES + dstoff[h2], pBl[h2] + (kof), 16u); \
    } \
} while (0)

    // ---- compute setup
    int wm = (wid & 1) * 64, wn = (wid >> 1) * 32;
    uint32_t a_off = (uint32_t)((wm + (lane & 15)) * ROWB + (lane >> 4) * 16);
    uint32_t b_off = (uint32_t)((wn + (lane & 7) + ((lane >> 4) << 3)) * ROWB +
                                ((lane >> 3) & 1) * 16);

    float acc[4][4][4];
#pragma unroll
    for (int i = 0; i < 4; i++)
#pragma unroll
        for (int j = 0; j < 4; j++)
#pragma unroll
            for (int q = 0; q < 4; q++) acc[i][j][q] = 0.f;

    const int nk = Kdim / BK;
    LOAD_STAGE(0, 0);
    CP_COMMIT();

    for (int ks = 0; ks < nk; ks++) {
        int s = ks & 1;
        if (ks + 1 < nk) {
            LOAD_STAGE(s ^ 1, (ks + 1) * BK);
            CP_COMMIT();
            CP_WAIT1();
        } else {
            CP_WAIT0();
        }
        __syncthreads();

        uint32_t sb = sbase + s * STAGE_BYTES;
#pragma unroll
        for (int h = 0; h < 2; h++) {  // two k16 steps per BK=32
            uint32_t ah[4][4], al[4][4], bh[4][2], bl[4][2];
#pragma unroll
            for (int i = 0; i < 4; i++) {
                uint32_t ad = sb + a_off + i * (16 * ROWB) + h * 32;
                LDSM_X4(ah[i], ad);
                LDSM_X4(al[i], ad + TILE_BYTES);
            }
#pragma unroll
            for (int jp = 0; jp < 2; jp++) {
                uint32_t tmp[4];
                uint32_t bd = sb + 2 * TILE_BYTES + b_off + jp * (16 * ROWB) + h * 32;
                LDSM_X4(tmp, bd);
                bh[jp * 2][0] = tmp[0]; bh[jp * 2][1] = tmp[1];
                bh[jp * 2 + 1][0] = tmp[2]; bh[jp * 2 + 1][1] = tmp[3];
                LDSM_X4(tmp, bd + TILE_BYTES);
                bl[jp * 2][0] = tmp[0]; bl[jp * 2][1] = tmp[1];
                bl[jp * 2 + 1][0] = tmp[2]; bl[jp * 2 + 1][1] = tmp[3];
            }
#pragma unroll
            for (int i = 0; i < 4; i++)
#pragma unroll
                for (int j = 0; j < 4; j++) {
                    MMA_BF16(acc[i][j], ah[i], bh[j]);
                    MMA_BF16(acc[i][j], ah[i], bl[j]);
                    MMA_BF16(acc[i][j], al[i], bh[j]);
                }
        }
        __syncthreads();
    }

    // ---- epilogue: direct global stores
    float* Co; int ncol0;
    if (MODE == 0) {
        if (n0 < I_DIM) { Co = d_g; ncol0 = n0; } else { Co = d_u; ncol0 = n0 - I_DIM; }
    } else {
        Co = d_eo; ncol0 = n0;
    }
    int rin = lane >> 2, cin = (lane & 3) * 2;
#pragma unroll
    for (int i = 0; i < 4; i++)
#pragma unroll
        for (int j = 0; j < 4; j++) {
            float* p = Co + (size_t)(row0 + wm + i * 16 + rin) * ldc +
                       ncol0 + wn + j * 8 + cin;
            *(float2*)p = make_float2(acc[i][j][0], acc[i][j][1]);
            *(float2*)(p + 8 * (size_t)ldc) = make_float2(acc[i][j][2], acc[i][j][3]);
        }
#undef LOAD_STAGE
}

// mid = silu(g) * u -> bf16 hi/lo
__global__ void act_kernel() {
    size_t idx = (size_t)blockIdx.x * 256 + threadIdx.x;  // float4 index
    float4 g = ((const float4*)d_g)[idx];
    float4 u = ((const float4*)d_u)[idx];
    float m0 = g.x / (1.f + expf(-g.x)) * u.x;
    float m1 = g.y / (1.f + expf(-g.y)) * u.y;
    float m2 = g.z / (1.f + expf(-g.z)) * u.z;
    float m3 = g.w / (1.f + expf(-g.w)) * u.w;
    ushort4 h, l;
    split2(m0, h.x, l.x); split2(m1, h.y, l.y);
    split2(m2, h.z, l.z); split2(m3, h.w, l.w);
    ((ushort4*)d_midhi)[idx] = h;
    ((ushort4*)d_midlo)[idx] = l;
}

// out[t] = w0*eo[row0] + w1*eo[row1]
__global__ void combine_kernel(float* __restrict__ out) {
    int t = blockIdx.x;
    int r0 = d_pairrow[t * 2 + 0], r1 = d_pairrow[t * 2 + 1];
    float w0 = d_topw[t * 2 + 0], w1 = d_topw[t * 2 + 1];
    int h4 = threadIdx.x;
    float4 a = ((const float4*)(d_eo + (size_t)r0 * H_DIM))[h4];
    float4 b = ((const float4*)(d_eo + (size_t)r1 * H_DIM))[h4];
    float4 o;
    o.x = w0 * a.x + w1 * b.x;
    o.y = w0 * a.y + w1 * b.y;
    o.z = w0 * a.z + w1 * b.z;
    o.w = w0 * a.w + w1 * b.w;
    ((float4*)(out + (size_t)t * H_DIM))[h4] = o;
}

// ---------------------------------------------------------------------------
extern "C" void kernel_launch(void* const* d_in, const int* in_sizes, int n_in,
                              void* d_out, int out_size) {
    const float* x  = (const float*)d_in[0];  // [4096, 1024]
    const float* gw = (const float*)d_in[1];  // [1024, 8]
    const float* Wg = (const float*)d_in[2];  // [8, 1024, 2048]
    const float* Wu = (const float*)d_in[3];  // [8, 1024, 2048]
    const float* Wd = (const float*)d_in[4];  // [8, 2048, 1024]
    float* out = (float*)d_out;               // final (4194304) then logits (32768)
    float* out_logits = out + (size_t)T_TOK * H_DIM;

    cudaFuncSetAttribute(mma_gemm_kernel<0>, cudaFuncAttributeMaxDynamicSharedMemorySize, SMEM_TOTAL);
    cudaFuncSetAttribute(mma_gemm_kernel<1>, cudaFuncAttributeMaxDynamicSharedMemorySize, SMEM_TOTAL);

    init_kernel<<<1, 256>>>();
    convx_kernel<<<(T_TOK * H_DIM / 4) / 256, 256>>>(x);
    wtrans_kernel<<<dim3(I_DIM / 32, H_DIM / 32, N_EXP), 256>>>(Wg, 0);
    wtrans_kernel<<<dim3(I_DIM / 32, H_DIM / 32, N_EXP), 256>>>(Wu, 1);
    wtrans_kernel<<<dim3(H_DIM / 32, I_DIM / 32, N_EXP), 256>>>(Wd, 2);

    router_kernel<<<T_TOK / 8, 256>>>(x, gw, out_logits);
    scan_kernel<<<1, 32>>>();
    scatter_kernel<<<T_TOK / 256, 256>>>();

    // GEMM1: [rows,1024] x W1^T -> d_g (n<2048) / d_u (n>=2048)
    mma_gemm_kernel<0><<<dim3(MAXROWS / BM, (2 * I_DIM) / BN), 256, SMEM_TOTAL>>>();
    act_kernel<<<(MAXROWS * (I_DIM / 4)) / 256, 256>>>();
    // GEMM2: [rows,2048] x Wd^T -> d_eo
    mma_gemm_kernel<1><<<dim3(MAXROWS / BM, H_DIM / BN), 256, SMEM_TOTAL>>>();
    combine_kernel<<<T_TOK, 256>>>(out);
}